// round 4
// baseline (speedup 1.0000x reference)
#include <cuda_runtime.h>
#include <math.h>

#define N     16384
#define S     8192
#define T     1024
#define GPT   16
#define CELLS 512
#define R2    0.0625f
#define KNB   10

// Distance formula matching XLA's contraction of sum((a-b)**2, -1):
// left-assoc reduction with fma fusion.
__device__ __forceinline__ float dist2(float dx, float dy, float dz) {
    return fmaf(dz, dz, fmaf(dy, dy, __fmul_rn(dx, dx)));
}

// ---------------- global scratch (no allocations allowed) ----------------
__device__ float g_xs[N], g_ys[N], g_zs[N];
__device__ int   g_s2o[N];
__device__ int   g_fps_sorted[S];   // winner layout-address per step (t>=1)
__device__ int   g_fps_idx[S];      // original index of each FPS sample
__device__ int   g_src[S * KNB];    // top-10 neighbor orig indices, -1 = invalid

// ---------------- K0: counting sort into 8x8x8 grid ----------------
// Layout trick: point with "sorted rank" d is stored at address a = (d&15)*T + (d>>4),
// so thread t's 16-point group lives at {g*T + t}, giving conflict-free LDS
// (lane-consecutive addresses) in the FPS kernel.
__global__ __launch_bounds__(T, 1) void sort_kernel(const float* __restrict__ pos) {
    __shared__ int hist[CELLS];
    __shared__ int scanbuf[CELLS];
    int tid = threadIdx.x;
    if (tid < CELLS) hist[tid] = 0;
    __syncthreads();
#pragma unroll
    for (int g = 0; g < GPT; ++g) {
        int i = g * T + tid;
        float x = pos[3*i], y = pos[3*i+1], z = pos[3*i+2];
        int cx = min(7, (int)(x * 8.0f));
        int cy = min(7, (int)(y * 8.0f));
        int cz = min(7, (int)(z * 8.0f));
        atomicAdd(&hist[(cz << 6) | (cy << 3) | cx], 1);
    }
    __syncthreads();
    if (tid < CELLS) scanbuf[tid] = hist[tid];
    __syncthreads();
    for (int off = 1; off < CELLS; off <<= 1) {
        int v = 0;
        if (tid < CELLS) { v = scanbuf[tid]; if (tid >= off) v += scanbuf[tid - off]; }
        __syncthreads();
        if (tid < CELLS) scanbuf[tid] = v;
        __syncthreads();
    }
    if (tid < CELLS) hist[tid] = scanbuf[tid] - hist[tid];  // exclusive -> cursor
    __syncthreads();
#pragma unroll
    for (int g = 0; g < GPT; ++g) {
        int i = g * T + tid;
        float x = pos[3*i], y = pos[3*i+1], z = pos[3*i+2];
        int cx = min(7, (int)(x * 8.0f));
        int cy = min(7, (int)(y * 8.0f));
        int cz = min(7, (int)(z * 8.0f));
        int c  = (cz << 6) | (cy << 3) | cx;
        int d  = atomicAdd(&hist[c], 1);
        int a  = (d & 15) * T + (d >> 4);
        g_xs[a] = x; g_ys[a] = y; g_zs[a] = z;
        g_s2o[a] = i;
    }
}

// ---------------- K1: pruned farthest point sampling (single block) ----------------
__global__ __launch_bounds__(T, 1) void fps_kernel(const float* __restrict__ pos) {
    extern __shared__ float sm[];
    float* xs = sm;
    float* ys = sm + N;
    float* zs = sm + 2 * N;
    __shared__ unsigned long long warpbest[32];
    __shared__ int s_w;
    int tid = threadIdx.x;
#pragma unroll
    for (int g = 0; g < GPT; ++g) {
        int a = g * T + tid;
        xs[a] = g_xs[a]; ys[a] = g_ys[a]; zs[a] = g_zs[a];
    }
    __syncthreads();

    // group centroid + radius (upper bound, padded)
    float qx = 0.f, qy = 0.f, qz = 0.f;
#pragma unroll
    for (int g = 0; g < GPT; ++g) {
        int a = g * T + tid;
        qx += xs[a]; qy += ys[a]; qz += zs[a];
    }
    qx *= (1.0f / GPT); qy *= (1.0f / GPT); qz *= (1.0f / GPT);
    float rr = 0.f;
#pragma unroll
    for (int g = 0; g < GPT; ++g) {
        int a = g * T + tid;
        float dx = xs[a] - qx, dy = ys[a] - qy, dz = zs[a] - qz;
        rr = fmaxf(rr, dx*dx + dy*dy + dz*dz);
    }
    float r = sqrtf(rr) + 1e-4f;

    float m[GPT];
#pragma unroll
    for (int g = 0; g < GPT; ++g) m[g] = 3.402823466e38f;
    float Mg   = 3.402823466e38f;
    int   midx = tid;
    float thr2 = 3.402823466e38f;   // force update on first step

    // first sample is original point 0
    float cx = pos[0], cy = pos[1], cz = pos[2];

    for (int t = 1; t < S; ++t) {
        float dqx = qx - cx, dqy = qy - cy, dqz = qz - cz;
        float dd  = dqx*dqx + dqy*dqy + dqz*dqz;
        if (dd < thr2) {
            float Ml = -1.0f; int il = tid;
#pragma unroll
            for (int g = 0; g < GPT; ++g) {
                int a = g * T + tid;
                float dx = __fsub_rn(xs[a], cx);
                float dy = __fsub_rn(ys[a], cy);
                float dz = __fsub_rn(zs[a], cz);
                float d  = dist2(dx, dy, dz);
                float nm = fminf(m[g], d);
                m[g] = nm;
                if (nm > Ml) { Ml = nm; il = a; }
            }
            Mg = Ml; midx = il;
            float thr = sqrtf(Mg) + r + 1e-3f;   // conservative skip bound
            thr2 = thr * thr;
        }
        unsigned long long key =
            (((unsigned long long)__float_as_uint(Mg)) << 32) | (unsigned)midx;
#pragma unroll
        for (int o = 16; o; o >>= 1) {
            unsigned long long k2 = __shfl_xor_sync(0xffffffffu, key, o);
            if (k2 > key) key = k2;
        }
        if ((tid & 31) == 0) warpbest[tid >> 5] = key;
        __syncthreads();
        if (tid < 32) {
            unsigned long long k = warpbest[tid];
#pragma unroll
            for (int o = 16; o; o >>= 1) {
                unsigned long long k2 = __shfl_xor_sync(0xffffffffu, k, o);
                if (k2 > k) k = k2;
            }
            if (tid == 0) {
                int w = (int)(unsigned)k;
                s_w = w;
                g_fps_sorted[t] = w;
            }
        }
        __syncthreads();
        int w = s_w;
        cx = xs[w]; cy = ys[w]; cz = zs[w];
    }
}

// ---------------- K1b: layout address -> original index ----------------
__global__ void mapidx_kernel() {
    int t = blockIdx.x * 256 + threadIdx.x;
    if (t >= S) return;
    g_fps_idx[t] = (t == 0) ? 0 : g_s2o[g_fps_sorted[t]];
}

// ---------------- K2: top-10 nearest neighbors per center ----------------
// 256 blocks x 256 threads: block = 32 centers x 8 slices of the point set.
__global__ __launch_bounds__(256, 4) void knn_kernel(const float* __restrict__ pos) {
    __shared__ float sd[32][80];
    __shared__ int   si[32][80];
    int tid   = threadIdx.x;
    int cslot = tid & 31;
    int slice = tid >> 5;
    int cidx  = blockIdx.x * 32 + cslot;
    int fi    = g_fps_idx[cidx];
    float cx = pos[3*fi], cy = pos[3*fi+1], cz = pos[3*fi+2];

    float bd[KNB]; int bi[KNB];
#pragma unroll
    for (int k = 0; k < KNB; ++k) { bd[k] = 3.402823466e38f; bi[k] = -1; }

    int start = slice * (N / 8);
    for (int j = 0; j < N / 8; ++j) {
        int p = start + j;
        float dx = __fsub_rn(pos[3*p],     cx);
        float dy = __fsub_rn(pos[3*p + 1], cy);
        float dz = __fsub_rn(pos[3*p + 2], cz);
        float d  = dist2(dx, dy, dz);
        if (d < bd[KNB - 1]) {
            bd[KNB - 1] = d; bi[KNB - 1] = p;
#pragma unroll
            for (int k = KNB - 1; k > 0; --k) {
                if (bd[k] < bd[k - 1]) {
                    float td = bd[k]; bd[k] = bd[k-1]; bd[k-1] = td;
                    int   ti = bi[k]; bi[k] = bi[k-1]; bi[k-1] = ti;
                } else break;
            }
        }
    }
#pragma unroll
    for (int k = 0; k < KNB; ++k) {
        sd[cslot][slice * KNB + k] = bd[k];
        si[cslot][slice * KNB + k] = bi[k];
    }
    __syncthreads();
    if (tid < 32) {
        int c = blockIdx.x * 32 + tid;
        int cur[8] = {0,0,0,0,0,0,0,0};
        for (int o = 0; o < KNB; ++o) {
            float best = 3.402823466e38f; int bs = 0;
#pragma unroll
            for (int s8 = 0; s8 < 8; ++s8) {
                if (cur[s8] < KNB) {
                    float v = sd[tid][s8 * KNB + cur[s8]];
                    if (v < best) { best = v; bs = s8; }
                }
            }
            int pi = si[tid][bs * KNB + cur[bs]];
            cur[bs]++;
            g_src[c * KNB + o] = (best <= R2) ? pi : -1;
        }
    }
}

// ---------------- K3: MLP (3->64 relu ->128) + max over valid neighbors ----------------
__global__ __launch_bounds__(128, 4) void mlp_kernel(const float* __restrict__ pos,
                                                     const float* __restrict__ W1,
                                                     const float* __restrict__ b1,
                                                     const float* __restrict__ W2,
                                                     const float* __restrict__ b2,
                                                     float* __restrict__ out) {
    __shared__ float h1[64];
    __shared__ int   ssrc[KNB];
    int tid = threadIdx.x;
    float w2r[64];
#pragma unroll
    for (int k = 0; k < 64; ++k) w2r[k] = W2[k * 128 + tid];
    float b2t = b2[tid];
    float w1x = 0.f, w1y = 0.f, w1z = 0.f, b1k = 0.f;
    if (tid < 64) { w1x = W1[tid]; w1y = W1[64 + tid]; w1z = W1[128 + tid]; b1k = b1[tid]; }

    for (int ci = 0; ci < 8; ++ci) {
        int i = blockIdx.x * 8 + ci;
        __syncthreads();
        if (tid < KNB) ssrc[tid] = g_src[i * KNB + tid];
        float pix = pos[3*i], piy = pos[3*i+1], piz = pos[3*i+2];
        __syncthreads();
        float mx = __int_as_float(0xff800000);
        bool any = false;
        for (int nb = 0; nb < KNB; ++nb) {
            int sp = ssrc[nb];
            if (sp < 0) break;   // invalids form a suffix (sorted by distance)
            any = true;
            if (tid < 64) {
                float rx = pos[3*sp]     - pix;
                float ry = pos[3*sp + 1] - piy;
                float rz = pos[3*sp + 2] - piz;
                // match XLA contraction: fma chain then + bias
                float h = fmaf(rz, w1z, fmaf(ry, w1y, __fmul_rn(rx, w1x))) + b1k;
                h1[tid] = fmaxf(h, 0.0f);
            }
            __syncthreads();
            float acc = b2t;
#pragma unroll
            for (int k = 0; k < 64; ++k) acc = fmaf(h1[k], w2r[k], acc);
            mx = fmaxf(mx, acc);
            __syncthreads();
        }
        out[i * 128 + tid] = any ? mx : 0.0f;
    }
}

// ---------------- K4: zero tail rows [S, N) ----------------
__global__ void zero_tail_kernel(float* __restrict__ out) {
    int i = blockIdx.x * blockDim.x + threadIdx.x;
    float4* o = (float4*)(out + S * 128);
    o[i] = make_float4(0.f, 0.f, 0.f, 0.f);   // (S*128)/4 = 262144 float4
}

extern "C" void kernel_launch(void* const* d_in, const int* in_sizes, int n_in,
                              void* d_out, int out_size) {
    const float* pos = (const float*)d_in[0];
    // d_in[1] = batch (unused, all zeros)
    const float* W1 = (const float*)d_in[2];
    const float* b1 = (const float*)d_in[3];
    const float* W2 = (const float*)d_in[4];
    const float* b2 = (const float*)d_in[5];
    float* out = (float*)d_out;

    static bool attr_set = false;
    if (!attr_set) {
        cudaFuncSetAttribute(fps_kernel, cudaFuncAttributeMaxDynamicSharedMemorySize,
                             3 * N * (int)sizeof(float));
        attr_set = true;
    }

    sort_kernel<<<1, T>>>(pos);
    fps_kernel<<<1, T, 3 * N * sizeof(float)>>>(pos);
    mapidx_kernel<<<(S + 255) / 256, 256>>>();
    knn_kernel<<<S / 32, 256>>>(pos);
    mlp_kernel<<<S / 8, 128>>>(pos, W1, b1, W2, b2, out);
    zero_tail_kernel<<<(S * 128 / 4) / 256, 256>>>(out);
}

// round 7
// speedup vs baseline: 1.1171x; 1.1171x over previous
#include <cuda_runtime.h>
#include <math.h>

#define N     16384
#define S     8192
#define T     1024
#define GPT   16
#define CELLS 512
#define R2    0.0625f
#define KNB   10

// Distance formula matching XLA's contraction of sum((a-b)**2, -1):
// left-assoc reduction with fma fusion.
__device__ __forceinline__ float dist2(float dx, float dy, float dz) {
    return fmaf(dz, dz, fmaf(dy, dy, __fmul_rn(dx, dx)));
}

// ---------------- global scratch (no allocations allowed) ----------------
__device__ float g_xs[N], g_ys[N], g_zs[N];
__device__ int   g_s2o[N];
__device__ int   g_fps_sorted[S];   // winner layout-address per step (t>=1)
__device__ int   g_fps_idx[S];      // original index of each FPS sample
__device__ int   g_src[S * KNB];    // top-10 neighbor orig indices, -1 = invalid

// ---------------- K0: counting sort into 8x8x8 grid ----------------
// Point with sorted rank d is stored at address a = (d&15)*T + (d>>4), so thread
// t's 16-point group lives at {g*T + t}: conflict-free, spatially compact groups.
__global__ __launch_bounds__(T, 1) void sort_kernel(const float* __restrict__ pos) {
    __shared__ int hist[CELLS];
    __shared__ int scanbuf[CELLS];
    int tid = threadIdx.x;
    if (tid < CELLS) hist[tid] = 0;
    __syncthreads();
#pragma unroll
    for (int g = 0; g < GPT; ++g) {
        int i = g * T + tid;
        float x = pos[3*i], y = pos[3*i+1], z = pos[3*i+2];
        int cx = min(7, (int)(x * 8.0f));
        int cy = min(7, (int)(y * 8.0f));
        int cz = min(7, (int)(z * 8.0f));
        atomicAdd(&hist[(cz << 6) | (cy << 3) | cx], 1);
    }
    __syncthreads();
    if (tid < CELLS) scanbuf[tid] = hist[tid];
    __syncthreads();
    for (int off = 1; off < CELLS; off <<= 1) {
        int v = 0;
        if (tid < CELLS) { v = scanbuf[tid]; if (tid >= off) v += scanbuf[tid - off]; }
        __syncthreads();
        if (tid < CELLS) scanbuf[tid] = v;
        __syncthreads();
    }
    if (tid < CELLS) hist[tid] = scanbuf[tid] - hist[tid];  // exclusive -> cursor
    __syncthreads();
#pragma unroll
    for (int g = 0; g < GPT; ++g) {
        int i = g * T + tid;
        float x = pos[3*i], y = pos[3*i+1], z = pos[3*i+2];
        int cx = min(7, (int)(x * 8.0f));
        int cy = min(7, (int)(y * 8.0f));
        int cz = min(7, (int)(z * 8.0f));
        int c  = (cz << 6) | (cy << 3) | cx;
        int d  = atomicAdd(&hist[c], 1);
        int a  = (d & 15) * T + (d >> 4);
        g_xs[a] = x; g_ys[a] = y; g_zs[a] = z;
        g_s2o[a] = i;
    }
}

// ---------------- K1: pruned farthest point sampling (single block) ----------------
// Per step: 1 barrier (parity double-buffered warp-best array), warp-level skip
// when no lane's group can change. Reductions reproduce EXACTLY the 64-bit
// (val,idx) max semantics of the validated R4 kernel:
//   max val first, then max idx among value-ties (two REDUX ops).
__global__ __launch_bounds__(T, 1) void fps_kernel(const float* __restrict__ pos) {
    extern __shared__ float sm[];
    float* xs = sm;
    float* ys = sm + N;
    float* zs = sm + 2 * N;
    __shared__ uint2 sbest[2][32];
    int tid  = threadIdx.x;
    int lane = tid & 31;
    int wid  = tid >> 5;
#pragma unroll
    for (int g = 0; g < GPT; ++g) {
        int a = g * T + tid;
        xs[a] = g_xs[a]; ys[a] = g_ys[a]; zs[a] = g_zs[a];
    }
    __syncthreads();

    // group centroid + radius (upper bound, padded)
    float qx = 0.f, qy = 0.f, qz = 0.f;
#pragma unroll
    for (int g = 0; g < GPT; ++g) {
        int a = g * T + tid;
        qx += xs[a]; qy += ys[a]; qz += zs[a];
    }
    qx *= (1.0f / GPT); qy *= (1.0f / GPT); qz *= (1.0f / GPT);
    float rr = 0.f;
#pragma unroll
    for (int g = 0; g < GPT; ++g) {
        int a = g * T + tid;
        float dx = xs[a] - qx, dy = ys[a] - qy, dz = zs[a] - qz;
        rr = fmaxf(rr, dx*dx + dy*dy + dz*dz);
    }
    float r = sqrtf(rr) + 1e-4f;

    float m[GPT];
#pragma unroll
    for (int g = 0; g < GPT; ++g) m[g] = 3.402823466e38f;
    float    Mg   = 3.402823466e38f;   // this lane's max over its groups
    int      midx = tid;
    float    thr2 = 3.402823466e38f;   // force update on first step
    unsigned wval = 0u;                // this warp's best (set at t=1; all warps update then)
    unsigned widx = 0u;

    // first sample is original point 0
    float cx = pos[0], cy = pos[1], cz = pos[2];

    for (int t = 1; t < S; ++t) {
        int p = t & 1;
        float dqx = qx - cx, dqy = qy - cy, dqz = qz - cz;
        float dd  = dqx*dqx + dqy*dqy + dqz*dqz;
        bool need = dd < thr2;
        unsigned upd = __ballot_sync(0xffffffffu, need);
        if (upd) {
            if (need) {
                float Ml = -1.0f; int il = tid;
#pragma unroll
                for (int g = 0; g < GPT; ++g) {
                    int a = g * T + tid;
                    float dx = __fsub_rn(xs[a], cx);
                    float dy = __fsub_rn(ys[a], cy);
                    float dz = __fsub_rn(zs[a], cz);
                    float d  = dist2(dx, dy, dz);
                    float nm = fminf(m[g], d);
                    m[g] = nm;
                    if (nm > Ml) { Ml = nm; il = a; }
                }
                Mg = Ml; midx = il;
                float thr = sqrtf(Mg) + r + 1e-3f;   // conservative skip bound
                thr2 = thr * thr;
            }
            // warp (val,idx) max: values >= 0 so uint order == float order;
            // tie-break = larger idx (identical to 64-bit key max of R4)
            unsigned vb   = __float_as_uint(Mg);
            unsigned wmax = __reduce_max_sync(0xffffffffu, vb);
            wval = wmax;
            widx = __reduce_max_sync(0xffffffffu, (vb == wmax) ? (unsigned)midx : 0u);
        }
        if (lane == 0) sbest[p][wid] = make_uint2(wval, widx);
        __syncthreads();
        // every warp redundantly reduces the 32 warp-bests (no second barrier),
        // same (val,idx) max semantics
        uint2    b    = sbest[p][lane];
        unsigned gmax = __reduce_max_sync(0xffffffffu, b.x);
        int      w    = (int)__reduce_max_sync(0xffffffffu, (b.x == gmax) ? b.y : 0u);
        if (tid == 0) g_fps_sorted[t] = w;
        cx = xs[w]; cy = ys[w]; cz = zs[w];
    }
}

// ---------------- K1b: layout address -> original index ----------------
__global__ void mapidx_kernel() {
    int t = blockIdx.x * 256 + threadIdx.x;
    if (t >= S) return;
    g_fps_idx[t] = (t == 0) ? 0 : g_s2o[g_fps_sorted[t]];
}

// ---------------- K2: top-10 nearest neighbors per center ----------------
// 512 blocks x 256 threads: block = 16 centers x 16 slices of the point set.
__global__ __launch_bounds__(256, 4) void knn_kernel(const float* __restrict__ pos) {
    __shared__ float sd[16][160];
    __shared__ int   si[16][160];
    int tid   = threadIdx.x;
    int cslot = tid & 15;
    int slice = tid >> 4;
    int cidx  = blockIdx.x * 16 + cslot;
    int fi    = g_fps_idx[cidx];
    float cx = pos[3*fi], cy = pos[3*fi+1], cz = pos[3*fi+2];

    float bd[KNB]; int bi[KNB];
#pragma unroll
    for (int k = 0; k < KNB; ++k) { bd[k] = 3.402823466e38f; bi[k] = -1; }

    int start = slice * (N / 16);
    for (int j = 0; j < N / 16; ++j) {
        int p = start + j;
        float dx = __fsub_rn(pos[3*p],     cx);
        float dy = __fsub_rn(pos[3*p + 1], cy);
        float dz = __fsub_rn(pos[3*p + 2], cz);
        float d  = dist2(dx, dy, dz);
        if (d < bd[KNB - 1]) {
            bd[KNB - 1] = d; bi[KNB - 1] = p;
#pragma unroll
            for (int k = KNB - 1; k > 0; --k) {
                if (bd[k] < bd[k - 1]) {
                    float td = bd[k]; bd[k] = bd[k-1]; bd[k-1] = td;
                    int   ti = bi[k]; bi[k] = bi[k-1]; bi[k-1] = ti;
                } else break;
            }
        }
    }
#pragma unroll
    for (int k = 0; k < KNB; ++k) {
        sd[cslot][slice * KNB + k] = bd[k];
        si[cslot][slice * KNB + k] = bi[k];
    }
    __syncthreads();
    if (tid < 16) {
        int c = blockIdx.x * 16 + tid;
        int cur[16];
#pragma unroll
        for (int s16 = 0; s16 < 16; ++s16) cur[s16] = 0;
        for (int o = 0; o < KNB; ++o) {
            float best = 3.402823466e38f; int bs = 0;
#pragma unroll
            for (int s16 = 0; s16 < 16; ++s16) {
                if (cur[s16] < KNB) {
                    float v = sd[tid][s16 * KNB + cur[s16]];
                    if (v < best) { best = v; bs = s16; }
                }
            }
            int pi = si[tid][bs * KNB + cur[bs]];
            cur[bs]++;
            g_src[c * KNB + o] = (best <= R2) ? pi : -1;
        }
    }
}

// ---------------- K3: MLP (3->64 relu ->128) + max over valid neighbors ----------------
__global__ __launch_bounds__(128, 4) void mlp_kernel(const float* __restrict__ pos,
                                                     const float* __restrict__ W1,
                                                     const float* __restrict__ b1,
                                                     const float* __restrict__ W2,
                                                     const float* __restrict__ b2,
                                                     float* __restrict__ out) {
    __shared__ float h1[64];
    __shared__ int   ssrc[KNB];
    int tid = threadIdx.x;
    float w2r[64];
#pragma unroll
    for (int k = 0; k < 64; ++k) w2r[k] = W2[k * 128 + tid];
    float b2t = b2[tid];
    float w1x = 0.f, w1y = 0.f, w1z = 0.f, b1k = 0.f;
    if (tid < 64) { w1x = W1[tid]; w1y = W1[64 + tid]; w1z = W1[128 + tid]; b1k = b1[tid]; }

    for (int ci = 0; ci < 8; ++ci) {
        int i = blockIdx.x * 8 + ci;
        __syncthreads();
        if (tid < KNB) ssrc[tid] = g_src[i * KNB + tid];
        float pix = pos[3*i], piy = pos[3*i+1], piz = pos[3*i+2];
        __syncthreads();
        float mx = __int_as_float(0xff800000);
        bool any = false;
        for (int nb = 0; nb < KNB; ++nb) {
            int sp = ssrc[nb];
            if (sp < 0) break;   // invalids form a suffix (sorted by distance)
            any = true;
            if (tid < 64) {
                float rx = pos[3*sp]     - pix;
                float ry = pos[3*sp + 1] - piy;
                float rz = pos[3*sp + 2] - piz;
                // match XLA contraction: fma chain then + bias
                float h = fmaf(rz, w1z, fmaf(ry, w1y, __fmul_rn(rx, w1x))) + b1k;
                h1[tid] = fmaxf(h, 0.0f);
            }
            __syncthreads();
            float acc = b2t;
#pragma unroll
            for (int k = 0; k < 64; ++k) acc = fmaf(h1[k], w2r[k], acc);
            mx = fmaxf(mx, acc);
            __syncthreads();
        }
        out[i * 128 + tid] = any ? mx : 0.0f;
    }
}

// ---------------- K4: zero tail rows [S, N) ----------------
__global__ void zero_tail_kernel(float* __restrict__ out) {
    int i = blockIdx.x * blockDim.x + threadIdx.x;
    float4* o = (float4*)(out + S * 128);
    o[i] = make_float4(0.f, 0.f, 0.f, 0.f);   // (S*128)/4 = 262144 float4
}

extern "C" void kernel_launch(void* const* d_in, const int* in_sizes, int n_in,
                              void* d_out, int out_size) {
    const float* pos = (const float*)d_in[0];
    // d_in[1] = batch (unused, all zeros)
    const float* W1 = (const float*)d_in[2];
    const float* b1 = (const float*)d_in[3];
    const float* W2 = (const float*)d_in[4];
    const float* b2 = (const float*)d_in[5];
    float* out = (float*)d_out;

    static bool attr_set = false;
    if (!attr_set) {
        cudaFuncSetAttribute(fps_kernel, cudaFuncAttributeMaxDynamicSharedMemorySize,
                             3 * N * (int)sizeof(float));
        attr_set = true;
    }

    sort_kernel<<<1, T>>>(pos);
    fps_kernel<<<1, T, 3 * N * sizeof(float)>>>(pos);
    mapidx_kernel<<<(S + 255) / 256, 256>>>();
    knn_kernel<<<S / 16, 256>>>(pos);
    mlp_kernel<<<S / 8, 128>>>(pos, W1, b1, W2, b2, out);
    zero_tail_kernel<<<(S * 128 / 4) / 256, 256>>>(out);
}

// round 8
// speedup vs baseline: 1.3470x; 1.2059x over previous
#include <cuda_runtime.h>
#include <math.h>

#define N     16384
#define S     8192
#define T     1024
#define GPT   16
#define CELLS 512
#define R2    0.0625f
#define KNB   10

// Distance formula matching XLA's contraction of sum((a-b)**2, -1):
// left-assoc reduction with fma fusion.
__device__ __forceinline__ float dist2(float dx, float dy, float dz) {
    return fmaf(dz, dz, fmaf(dy, dy, __fmul_rn(dx, dx)));
}

__device__ __forceinline__ int morton3(int x, int y, int z) {
    int m = 0;
#pragma unroll
    for (int b = 0; b < 3; ++b)
        m |= (((x >> b) & 1) << (3*b)) | (((y >> b) & 1) << (3*b + 1)) |
             (((z >> b) & 1) << (3*b + 2));
    return m;
}

// ---------------- global scratch (no allocations allowed) ----------------
__device__ float g_xs[N], g_ys[N], g_zs[N];
__device__ int   g_s2o[N];
__device__ int   g_fps_idx[S];      // original index of each FPS sample
__device__ int   g_src[S * KNB];    // top-10 neighbor orig indices, -1 = invalid

// ---------------- K0: counting sort into Morton-ordered 8x8x8 grid ----------------
// Point with sorted rank d is stored at address a = (d&15)*T + (d>>4): thread t's
// 16-point group = ranks [16t,16t+16) (compact); warp's 512 ranks = 16 MORTON-
// consecutive cells = compact box (not a slab) -> fewer prune failures per warp.
__global__ __launch_bounds__(T, 1) void sort_kernel(const float* __restrict__ pos) {
    __shared__ int hist[CELLS];
    __shared__ int scanbuf[CELLS];
    int tid = threadIdx.x;
    if (tid < CELLS) hist[tid] = 0;
    __syncthreads();
#pragma unroll
    for (int g = 0; g < GPT; ++g) {
        int i = g * T + tid;
        float x = pos[3*i], y = pos[3*i+1], z = pos[3*i+2];
        int cx = min(7, (int)(x * 8.0f));
        int cy = min(7, (int)(y * 8.0f));
        int cz = min(7, (int)(z * 8.0f));
        atomicAdd(&hist[morton3(cx, cy, cz)], 1);
    }
    __syncthreads();
    if (tid < CELLS) scanbuf[tid] = hist[tid];
    __syncthreads();
    for (int off = 1; off < CELLS; off <<= 1) {
        int v = 0;
        if (tid < CELLS) { v = scanbuf[tid]; if (tid >= off) v += scanbuf[tid - off]; }
        __syncthreads();
        if (tid < CELLS) scanbuf[tid] = v;
        __syncthreads();
    }
    if (tid < CELLS) hist[tid] = scanbuf[tid] - hist[tid];  // exclusive -> cursor
    __syncthreads();
#pragma unroll
    for (int g = 0; g < GPT; ++g) {
        int i = g * T + tid;
        float x = pos[3*i], y = pos[3*i+1], z = pos[3*i+2];
        int cx = min(7, (int)(x * 8.0f));
        int cy = min(7, (int)(y * 8.0f));
        int cz = min(7, (int)(z * 8.0f));
        int c  = morton3(cx, cy, cz);
        int d  = atomicAdd(&hist[c], 1);
        int a  = (d & 15) * T + (d >> 4);
        g_xs[a] = x; g_ys[a] = y; g_zs[a] = z;
        g_s2o[a] = i;
    }
}

// ---------------- K1: pruned farthest point sampling (single block) ----------------
// Exact-by-construction argmax semantics: value max, tie-break = LOWEST ORIGINAL
// index (jnp.argmax first-occurrence), carried as key (~orig<<14)|layout through
// lane-local scan, warp REDUX, and block REDUX. Stale per-warp state is exact
// (prune proof: skipped groups provably unchanged).
__global__ __launch_bounds__(T, 1) void fps_kernel(const float* __restrict__ pos) {
    extern __shared__ float sm[];
    float2* sxy = (float2*)sm;        // 128KB
    float*  sz  = sm + 2 * N;         // 64KB
    __shared__ uint2 sbest[2][32];
    int tid  = threadIdx.x;
    int lane = tid & 31;
    int wid  = tid >> 5;
    if (tid == 0) g_fps_idx[0] = 0;

    unsigned pk[GPT/2];
#pragma unroll
    for (int g = 0; g < GPT/2; ++g) pk[g] = 0u;
#pragma unroll
    for (int g = 0; g < GPT; ++g) {
        int a = g * T + tid;
        sxy[a] = make_float2(g_xs[a], g_ys[a]);
        sz[a]  = g_zs[a];
        unsigned ko = (~(unsigned)g_s2o[a]) & 0x3FFFu;   // max(~orig) == min(orig)
        pk[g >> 1] |= ko << (16 * (g & 1));
    }
    __syncthreads();

    // group centroid + radius (upper bound, padded)
    float qx = 0.f, qy = 0.f, qz = 0.f;
#pragma unroll
    for (int g = 0; g < GPT; ++g) {
        int a = g * T + tid;
        float2 xy = sxy[a];
        qx += xy.x; qy += xy.y; qz += sz[a];
    }
    qx *= (1.0f / GPT); qy *= (1.0f / GPT); qz *= (1.0f / GPT);
    float rr = 0.f;
#pragma unroll
    for (int g = 0; g < GPT; ++g) {
        int a = g * T + tid;
        float2 xy = sxy[a];
        float dx = xy.x - qx, dy = xy.y - qy, dz = sz[a] - qz;
        rr = fmaxf(rr, dx*dx + dy*dy + dz*dz);
    }
    float r = sqrtf(rr) + 1e-4f;

    float m[GPT];
#pragma unroll
    for (int g = 0; g < GPT; ++g) m[g] = 3.402823466e38f;
    float    Mg   = 3.402823466e38f;
    unsigned kb   = 0u;                // korig of lane argmax
    unsigned ab   = (unsigned)tid;     // layout addr of lane argmax
    float    thr2 = 3.402823466e38f;   // force update at t=1
    unsigned wval = 0u, wk2 = 0u;      // warp best (set at t=1)

    float cx = pos[0], cy = pos[1], cz = pos[2];

    for (int t = 1; t < S; ++t) {
        int p = t & 1;
        float dqx = qx - cx, dqy = qy - cy, dqz = qz - cz;
        float dd  = dqx*dqx + dqy*dqy + dqz*dqz;
        bool need = dd < thr2;
        unsigned upd = __ballot_sync(0xffffffffu, need);
        if (upd) {
            if (need) {
                float Ml = -1.0f; unsigned kbl = 0u, abl = 0u;
#pragma unroll
                for (int g = 0; g < GPT; ++g) {
                    int a = g * T + tid;
                    float2 xy = sxy[a];
                    float dx = __fsub_rn(xy.x, cx);
                    float dy = __fsub_rn(xy.y, cy);
                    float dz = __fsub_rn(sz[a], cz);
                    float d  = dist2(dx, dy, dz);
                    float nm = fminf(m[g], d);
                    m[g] = nm;
                    unsigned ko = (pk[g >> 1] >> (16 * (g & 1))) & 0xFFFFu;
                    if (nm > Ml)                    { Ml = nm; kbl = ko; abl = (unsigned)a; }
                    else if (nm == Ml && ko > kbl)  {          kbl = ko; abl = (unsigned)a; }
                }
                Mg = Ml; kb = kbl; ab = abl;
                float thr = sqrtf(Mg) + r + 1e-3f;   // conservative skip bound
                thr2 = thr * thr;
            }
            unsigned vb   = __float_as_uint(Mg);
            unsigned wmax = __reduce_max_sync(0xffffffffu, vb);
            wval = wmax;
            wk2  = __reduce_max_sync(0xffffffffu,
                                     (vb == wmax) ? ((kb << 14) | ab) : 0u);
        }
        if (lane == 0) sbest[p][wid] = make_uint2(wval, wk2);
        __syncthreads();
        uint2    b    = sbest[p][lane];
        unsigned gmax = __reduce_max_sync(0xffffffffu, b.x);
        unsigned gk2  = __reduce_max_sync(0xffffffffu, (b.x == gmax) ? b.y : 0u);
        int w = (int)(gk2 & 0x3FFFu);
        if (tid == 0) g_fps_idx[t] = (int)((~(gk2 >> 14)) & 0x3FFFu);
        float2 cxy = sxy[w];
        cx = cxy.x; cy = cxy.y; cz = sz[w];
    }
}

// ---------------- K2: top-10 nearest neighbors, 1 warp per center ----------------
// Block: 512 threads = 16 warps = 16 centers; all of pos cached in 192KB smem
// (stride-3 float access -> conflict-free). Lane-interleaved scan keeps each
// lane's list ascending in p; merge tie-breaks (d, then p) = reference top_k.
__global__ __launch_bounds__(512, 1) void knn_kernel(const float* __restrict__ pos) {
    extern __shared__ float sp[];     // 3*N floats = 192KB
    int tid = threadIdx.x, lane = tid & 31, w = tid >> 5;
    const float4* p4 = (const float4*)pos;
    float4* s4 = (float4*)sp;
#pragma unroll
    for (int i = 0; i < (3 * N / 4) / 512; ++i)       // 24 iterations
        s4[i * 512 + tid] = p4[i * 512 + tid];
    __syncthreads();

    int c  = blockIdx.x * 16 + w;
    int fi = g_fps_idx[c];
    float cx = sp[3*fi], cy = sp[3*fi+1], cz = sp[3*fi+2];

    float bd[KNB]; int bi[KNB];
#pragma unroll
    for (int k = 0; k < KNB; ++k) { bd[k] = 3.402823466e38f; bi[k] = -1; }

    for (int j = 0; j < N / 32; ++j) {
        int p = j * 32 + lane;
        float dx = __fsub_rn(sp[3*p],     cx);
        float dy = __fsub_rn(sp[3*p + 1], cy);
        float dz = __fsub_rn(sp[3*p + 2], cz);
        float d  = dist2(dx, dy, dz);
        if (d < bd[KNB - 1]) {
            bd[KNB - 1] = d; bi[KNB - 1] = p;
#pragma unroll
            for (int k = KNB - 1; k > 0; --k) {
                if (bd[k] < bd[k - 1]) {
                    float td = bd[k]; bd[k] = bd[k-1]; bd[k-1] = td;
                    int   ti = bi[k]; bi[k] = bi[k-1]; bi[k-1] = ti;
                } else break;
            }
        }
    }

    // 32-way merge: 10 rounds of (min d, tie min p) selection via REDUX.
    int cur = 0;
    for (int o = 0; o < KNB; ++o) {
        float hd_f; int hp;
        {   // register-array extraction without dynamic indexing (SEL chains)
            float fv = bd[0]; int iv = bi[0];
#pragma unroll
            for (int k = 1; k < KNB; ++k) { fv = (cur == k) ? bd[k] : fv; iv = (cur == k) ? bi[k] : iv; }
            hd_f = fv; hp = iv;
        }
        unsigned hd   = __float_as_uint(hd_f);
        unsigned dmin = __reduce_min_sync(0xffffffffu, hd);
        int cand = (hd == dmin) ? hp : 0x7FFFFFFF;
        int pmin = (int)__reduce_min_sync(0xffffffffu, (unsigned)cand);
        if (lane == 0)
            g_src[c * KNB + o] = (__uint_as_float(dmin) <= R2) ? pmin : -1;
        if (hd == dmin && hp == pmin) cur++;
    }
}

// ---------------- K3: MLP (3->64 relu ->128) + max over valid neighbors ----------------
// Two neighbors per barrier pair: thread-half 0 computes h1 for nb, half 1 for nb+1.
__global__ __launch_bounds__(128, 4) void mlp_kernel(const float* __restrict__ pos,
                                                     const float* __restrict__ W1,
                                                     const float* __restrict__ b1,
                                                     const float* __restrict__ W2,
                                                     const float* __restrict__ b2,
                                                     float* __restrict__ out) {
    __shared__ float h1[2][64];
    __shared__ int   ssrc[KNB];
    int tid  = threadIdx.x;
    int half = tid >> 6;
    int hid  = tid & 63;
    float w2r[64];
#pragma unroll
    for (int k = 0; k < 64; ++k) w2r[k] = W2[k * 128 + tid];
    float b2t = b2[tid];
    float w1x = W1[hid], w1y = W1[64 + hid], w1z = W1[128 + hid], b1k = b1[hid];

    for (int ci = 0; ci < 8; ++ci) {
        int i = blockIdx.x * 8 + ci;
        __syncthreads();
        if (tid < KNB) ssrc[tid] = g_src[i * KNB + tid];
        float pix = pos[3*i], piy = pos[3*i+1], piz = pos[3*i+2];
        __syncthreads();
        int cnt = 0;
#pragma unroll
        for (int k = 0; k < KNB; ++k) cnt += (ssrc[k] >= 0);  // invalids are a suffix
        float mx = __int_as_float(0xff800000);
        for (int nb = 0; nb < cnt; nb += 2) {
            int mynb = nb + half;
            if (mynb < cnt) {
                int sp = ssrc[mynb];
                float rx = pos[3*sp]     - pix;
                float ry = pos[3*sp + 1] - piy;
                float rz = pos[3*sp + 2] - piz;
                float h = fmaf(rz, w1z, fmaf(ry, w1y, __fmul_rn(rx, w1x))) + b1k;
                h1[half][hid] = fmaxf(h, 0.0f);
            }
            __syncthreads();
            float acc = b2t;
#pragma unroll
            for (int k = 0; k < 64; ++k) acc = fmaf(h1[0][k], w2r[k], acc);
            mx = fmaxf(mx, acc);
            if (nb + 1 < cnt) {
                float acc1 = b2t;
#pragma unroll
                for (int k = 0; k < 64; ++k) acc1 = fmaf(h1[1][k], w2r[k], acc1);
                mx = fmaxf(mx, acc1);
            }
            __syncthreads();
        }
        out[i * 128 + tid] = (cnt > 0) ? mx : 0.0f;
    }
}

// ---------------- K4: zero tail rows [S, N) ----------------
__global__ void zero_tail_kernel(float* __restrict__ out) {
    int i = blockIdx.x * blockDim.x + threadIdx.x;
    float4* o = (float4*)(out + S * 128);
    o[i] = make_float4(0.f, 0.f, 0.f, 0.f);
}

extern "C" void kernel_launch(void* const* d_in, const int* in_sizes, int n_in,
                              void* d_out, int out_size) {
    const float* pos = (const float*)d_in[0];
    const float* W1 = (const float*)d_in[2];
    const float* b1 = (const float*)d_in[3];
    const float* W2 = (const float*)d_in[4];
    const float* b2 = (const float*)d_in[5];
    float* out = (float*)d_out;

    static bool attr_set = false;
    if (!attr_set) {
        cudaFuncSetAttribute(fps_kernel, cudaFuncAttributeMaxDynamicSharedMemorySize,
                             3 * N * (int)sizeof(float));
        cudaFuncSetAttribute(knn_kernel, cudaFuncAttributeMaxDynamicSharedMemorySize,
                             3 * N * (int)sizeof(float));
        attr_set = true;
    }

    sort_kernel<<<1, T>>>(pos);
    fps_kernel<<<1, T, 3 * N * sizeof(float)>>>(pos);
    knn_kernel<<<S / 16, 512, 3 * N * sizeof(float)>>>(pos);
    mlp_kernel<<<S / 8, 128>>>(pos, W1, b1, W2, b2, out);
    zero_tail_kernel<<<(S * 128 / 4) / 256, 256>>>(out);
}